// round 7
// baseline (speedup 1.0000x reference)
#include <cuda_runtime.h>

// PixelWiseRNN: h_t = tanh(w_ih*x_t + b_ih + w_hh*h_{t-1} + b_hh), h_0 = 0
// x: (B, T, Z, H, W) fp32, params: (Z, H, W) fp32, out: (B, T, Z, H, W) fp32
// B=4, T=256, Z=16, H=64, W=64  ->  P = Z*H*W = 65536 pixels per batch.
//
// R6: double-buffered time-blocking. Each warp issues block k+1's 8 loads
// BEFORE computing block k, so its own load-wait overlaps its compute+stores
// (R5 showed in-flight bytes are ample; the exposed per-block load-wait was
// the residual). Stores issue immediately per step (no staging burst).

#define RNN_B 4
#define RNN_T 256
#define RNN_P 65536   // Z*H*W
#define TB 8          // timesteps per block

__device__ __forceinline__ float hw_tanh(float z)
{
    float r;
    asm("tanh.approx.f32 %0, %1;" : "=f"(r) : "f"(z));
    return r;
}

__global__ __launch_bounds__(256) void pixel_rnn_kernel(
    const float* __restrict__ x,
    const float* __restrict__ w_ih,
    const float* __restrict__ w_hh,
    const float* __restrict__ b_ih,
    const float* __restrict__ b_hh,
    float* __restrict__ out)
{
    const int gid = blockIdx.x * blockDim.x + threadIdx.x;   // [0, B*P)
    const int b = gid >> 16;          // gid / P
    const int p = gid & (RNN_P - 1);  // gid % P

    const float wi   = w_ih[p];
    const float wh   = w_hh[p];
    const float bias = b_ih[p] + b_hh[p];

    const size_t base = (size_t)b * RNN_T * RNN_P + p;
    const float* __restrict__ xp = x + base;
    float* __restrict__ op = out + base;

    float h = 0.0f;

    // Preload block 0.
    float xa[TB];
    #pragma unroll
    for (int i = 0; i < TB; i++)
        xa[i] = xp[(size_t)i * RNN_P];

    // Outer loop unrolled by 2 so the xa<-xb copies become register renames.
    #pragma unroll 2
    for (int tb = 0; tb < RNN_T; tb += TB) {
        const int tn = tb + TB;

        // Issue next block's loads first (off the dependency chain).
        float xb[TB];
        if (tn < RNN_T) {
            #pragma unroll
            for (int i = 0; i < TB; i++)
                xb[i] = xp[(size_t)(tn + i) * RNN_P];
        }

        // Serial recurrence over this block; store each h immediately.
        #pragma unroll
        for (int i = 0; i < TB; i++) {
            const float a = fmaf(wi, xa[i], bias);
            h = hw_tanh(fmaf(wh, h, a));
            op[(size_t)(tb + i) * RNN_P] = h;
        }

        #pragma unroll
        for (int i = 0; i < TB; i++)
            xa[i] = xb[i];
    }
}

extern "C" void kernel_launch(void* const* d_in, const int* in_sizes, int n_in,
                              void* d_out, int out_size)
{
    const float* x    = (const float*)d_in[0];
    const float* w_ih = (const float*)d_in[1];
    const float* w_hh = (const float*)d_in[2];
    const float* b_ih = (const float*)d_in[3];
    const float* b_hh = (const float*)d_in[4];
    float* out = (float*)d_out;

    const int total_threads = RNN_B * RNN_P;   // 262144
    const int block = 256;
    const int grid = total_threads / block;    // 1024

    pixel_rnn_kernel<<<grid, block>>>(x, w_ih, w_hh, b_ih, b_hh, out);
}

// round 11
// speedup vs baseline: 1.0329x; 1.0329x over previous
#include <cuda_runtime.h>

// PixelWiseRNN: h_t = tanh(w_ih*x_t + b_ih + w_hh*h_{t-1} + b_hh), h_0 = 0
// x: (B, T, Z, H, W) fp32, params: (Z, H, W) fp32, out: (B, T, Z, H, W) fp32
// B=4, T=256, Z=16, H=64, W=64  ->  P = Z*H*W = 65536 pixels per batch.
//
// R7: lesson from R1/R2/R6 — manual software pipelines lose to ptxas's own
// load front-batching. Simplest possible body: load x[t] in-loop (independent
// of h, so with unroll 8 ptxas hoists all 8 LDGs ahead of the serial tanh
// chain), store immediately per step. hw tanh (MUFU.TANH) keeps the chain
// at ~24 cyc/step. 262144 threads, 256/block, occ ~80%.

#define RNN_B 4
#define RNN_T 256
#define RNN_P 65536   // Z*H*W

__device__ __forceinline__ float hw_tanh(float z)
{
    float r;
    asm("tanh.approx.f32 %0, %1;" : "=f"(r) : "f"(z));
    return r;
}

__global__ __launch_bounds__(256) void pixel_rnn_kernel(
    const float* __restrict__ x,
    const float* __restrict__ w_ih,
    const float* __restrict__ w_hh,
    const float* __restrict__ b_ih,
    const float* __restrict__ b_hh,
    float* __restrict__ out)
{
    const int gid = blockIdx.x * blockDim.x + threadIdx.x;   // [0, B*P)
    const int b = gid >> 16;          // gid / P
    const int p = gid & (RNN_P - 1);  // gid % P

    const float wi   = w_ih[p];
    const float wh   = w_hh[p];
    const float bias = b_ih[p] + b_hh[p];

    const size_t base = (size_t)b * RNN_T * RNN_P + p;
    const float* __restrict__ xp = x + base;
    float* __restrict__ op = out + base;

    float h = 0.0f;

    #pragma unroll 8
    for (int t = 0; t < RNN_T; t++) {
        const float xv = xp[(size_t)t * RNN_P];   // h-independent: ptxas
                                                  // front-batches 8 of these
        const float a = fmaf(wi, xv, bias);       // off the h-chain
        h = hw_tanh(fmaf(wh, h, a));
        op[(size_t)t * RNN_P] = h;
    }
}

extern "C" void kernel_launch(void* const* d_in, const int* in_sizes, int n_in,
                              void* d_out, int out_size)
{
    const float* x    = (const float*)d_in[0];
    const float* w_ih = (const float*)d_in[1];
    const float* w_hh = (const float*)d_in[2];
    const float* b_ih = (const float*)d_in[3];
    const float* b_hh = (const float*)d_in[4];
    float* out = (float*)d_out;

    const int total_threads = RNN_B * RNN_P;   // 262144
    const int block = 256;
    const int grid = total_threads / block;    // 1024

    pixel_rnn_kernel<<<grid, block>>>(x, w_ih, w_hh, b_ih, b_hh, out);
}